// round 13
// baseline (speedup 1.0000x reference)
#include <cuda_runtime.h>
#include <cuda_bf16.h>
#include <math.h>

#define NN 50000
#define NFEAT 128
#define RDIM 128
#define NREL 500
#define NE 800000
#define NEN 100000
#define NET 900000
#define DOUT 128
#define ALPHA 0.2f

// output section offsets (floats)
#define OFF1 (NN*DOUT)            /* out_rel */
#define OFF2 (OFF1 + NREL*DOUT)   /* elu(h_num2) */
#define OFF3 (OFF2 + NN*DOUT)     /* elu(h_unif2) */

// ---------------- scratch (device globals; no allocation allowed) ----------------
static __device__ int  g_cnt[NN];          // zero-init at load; re-zeroed by k_setup2 each run
static __device__ int  g_rp[NN+1];
static __device__ int  g_cur[NN];
static __device__ int4 g_meta[NET];                       // (e1, idx, ta, tb)
static __device__ __align__(16) float2 g_ss1[NN];
static __device__ __align__(16) float2 g_sd1[NN];
static __device__ __align__(16) float g_cat1[(size_t)NN*512];   // [n][h][wx(128) we(128)]
static __device__ __align__(16) float g_x2[(size_t)NN*128];
static __device__ float g_s2s[NN], g_s2d[NN];
static __device__ __align__(16) float g_acc2[(size_t)NN*512];   // [n][wx wo sx/c so/c]
static __device__ float g_rs2[NN];
static __device__ __align__(16) float g_vvec[6][128];     // [h*3+w], w: 0=src 1=dst 2=rel
static __device__ __align__(8)  float g_srel1[2*NREL];    // [t*2+h]
static __device__ __align__(16) float g_w2[3][128];
static __device__ float g_s2rel[NREL];
static __device__ __align__(16) float g_outrel[NREL*128];
// bf16 hi/lo weights in ORIGINAL [o][k] layout (k contiguous)
static __device__ __align__(16) __nv_bfloat16 g_Bh1[2*64*384];
static __device__ __align__(16) __nv_bfloat16 g_Bl1[2*64*384];
static __device__ __align__(16) __nv_bfloat16 g_Bh2[128*384];
static __device__ __align__(16) __nv_bfloat16 g_Bl2[128*384];

// ---------------- helpers ----------------
__device__ __forceinline__ float lrelu(float z){ return z > 0.f ? z : ALPHA*z; }
__device__ __forceinline__ float eluf(float z){ return z > 0.f ? z : (__expf(z) - 1.f); }
__device__ __forceinline__ float d4(float4 a, float4 b){
    return a.x*b.x + a.y*b.y + a.z*b.z + a.w*b.w;
}
__device__ __forceinline__ float wredsum(float v){
    #pragma unroll
    for (int o = 16; o; o >>= 1) v += __shfl_xor_sync(0xFFFFFFFFu, v, o);
    return v;
}
__device__ __forceinline__ void fma4(float4 &acc, float s, float4 v){
    acc.x += s*v.x; acc.y += s*v.y; acc.z += s*v.z; acc.w += s*v.w;
}
__device__ __forceinline__ unsigned smem_u32(const void* p){
    return (unsigned)__cvta_generic_to_shared(p);
}
__device__ __forceinline__ void ldsm4(unsigned &r0, unsigned &r1, unsigned &r2, unsigned &r3, unsigned a){
    asm volatile("ldmatrix.sync.aligned.m8n8.x4.shared.b16 {%0,%1,%2,%3},[%4];"
        : "=r"(r0),"=r"(r1),"=r"(r2),"=r"(r3) : "r"(a));
}
__device__ __forceinline__ void mmabf(float* d, const unsigned* a, const unsigned* b){
    asm volatile("mma.sync.aligned.m16n8k16.row.col.f32.bf16.bf16.f32 "
        "{%0,%1,%2,%3},{%4,%5,%6,%7},{%8,%9},{%0,%1,%2,%3};"
        : "+f"(d[0]),"+f"(d[1]),"+f"(d[2]),"+f"(d[3])
        : "r"(a[0]),"r"(a[1]),"r"(a[2]),"r"(a[3]),"r"(b[0]),"r"(b[1]));
}
__device__ __forceinline__ void cvt_store_row(__nv_bfloat16* dh, __nv_bfloat16* dl, float4 v){
    __nv_bfloat162 h0 = __floats2bfloat162_rn(v.x, v.y);
    __nv_bfloat162 h1 = __floats2bfloat162_rn(v.z, v.w);
    __nv_bfloat162 l0 = __floats2bfloat162_rn(v.x - __low2float(h0),
                                              v.y - __high2float(h0));
    __nv_bfloat162 l1 = __floats2bfloat162_rn(v.z - __low2float(h1),
                                              v.w - __high2float(h1));
    *(__nv_bfloat162*)(dh)     = h0;
    *(__nv_bfloat162*)(dh + 2) = h1;
    *(__nv_bfloat162*)(dl)     = l0;
    *(__nv_bfloat162*)(dl + 2) = l1;
}

// ---------------- fused setup 1: hist + weight split/fold + out_rel ----------------
#define HIST_BLKS ((NET + 255)/256)                 // 3516
#define PREP_TOT (99456 + NREL*128)                 // 163456
#define PREP_BLKS ((PREP_TOT + 255)/256)            // 639
__global__ void k_setup1(const int* __restrict__ el, const int* __restrict__ eln,
                         const float* __restrict__ ah, const float* __restrict__ a2h,
                         const float* __restrict__ ao, const float* __restrict__ a2o,
                         const float* __restrict__ rel, const float* __restrict__ W,
                         float* __restrict__ out){
    if (blockIdx.x < HIST_BLKS){
        int i = blockIdx.x*256 + threadIdx.x;
        if (i >= NET) return;
        int n = (i < NE) ? __ldcs(el + i) : __ldcs(eln + i - NE);
        atomicAdd(&g_cnt[n], 1);
        return;
    }
    int id = (blockIdx.x - HIST_BLKS)*256 + threadIdx.x;
    if (id < 49152){
        float v = ah[id];
        __nv_bfloat16 h = __float2bfloat16(v);
        g_Bh1[id] = h;
        g_Bl1[id] = __float2bfloat16(v - __bfloat162float(h));
    } else if (id < 98304){
        int j = id - 49152;
        float v = ao[j];
        __nv_bfloat16 h = __float2bfloat16(v);
        g_Bh2[j] = h;
        g_Bl2[j] = __float2bfloat16(v - __bfloat162float(h));
    } else if (id < 99072){
        int j = id - 98304;
        int m = j / 128, k = j % 128;
        int h = m / 3, w = m % 3;
        float s = 0.f;
        #pragma unroll 4
        for (int o = 0; o < 64; o++)
            s += a2h[h*64 + o] * ah[h*24576 + o*384 + w*128 + k];
        g_vvec[m][k] = s;
    } else if (id < 99456){
        int j = id - 99072;
        int m = j / 128, k = j % 128;
        float s = 0.f;
        #pragma unroll 4
        for (int o = 0; o < 128; o++)
            s += a2o[o] * ao[o*384 + m*128 + k];
        g_w2[m][k] = s;
    } else if (id < PREP_TOT){
        int j = id - 99456;                    // out_rel = rel @ W
        int t = j / 128, o = j % 128;
        float s = 0.f;
        #pragma unroll 4
        for (int k = 0; k < 128; k++) s += rel[t*128 + k] * W[k*128 + o];
        g_outrel[j] = s;
        out[OFF1 + j] = s;
    }
}

// ---------------- fused setup 2: scan + srel + sdots1 ----------------
__global__ void k_setup2(const float* __restrict__ x, const float* __restrict__ rel){
    if (blockIdx.x == 0){
        // exclusive scan of g_cnt -> g_rp/g_cur (256 threads)
        __shared__ int sp[256];
        int t = threadIdx.x;
        const int C = (NN + 255) / 256;   // 196
        int base = t * C;
        int s = 0;
        for (int i = 0; i < C; i++){ int idx = base + i; if (idx < NN) s += g_cnt[idx]; }
        sp[t] = s; __syncthreads();
        for (int off = 1; off < 256; off <<= 1){
            int v = (t >= off) ? sp[t - off] : 0;
            __syncthreads();
            sp[t] += v;
            __syncthreads();
        }
        int pre = (t == 0) ? 0 : sp[t-1];
        for (int i = 0; i < C; i++){
            int idx = base + i;
            if (idx < NN){
                int c = g_cnt[idx];
                g_rp[idx] = pre; g_cur[idx] = pre; pre += c;
                g_cnt[idx] = 0;                    // self-clean for next run
            }
        }
        if (t == 255) g_rp[NN] = NET;
        return;
    }
    if (blockIdx.x <= 6){
        // srel: per-relation scalar folds
        int id = (blockIdx.x - 1)*256 + threadIdx.x;
        if (id < 1000){
            int t = id >> 1, h = id & 1;
            const float* v = g_vvec[h*3 + 2];
            float s = 0.f;
            #pragma unroll 4
            for (int k = 0; k < 128; k++) s += rel[t*128 + k] * v[k];
            g_srel1[id] = s;
        } else if (id < 1500){
            int t = id - 1000;
            float s = 0.f;
            #pragma unroll 4
            for (int k = 0; k < 128; k++) s += g_outrel[t*128 + k] * g_w2[2][k];
            g_s2rel[t] = s;
        }
        return;
    }
    // sdots1
    int w = (blockIdx.x - 7)*8 + (threadIdx.x >> 5);
    int l = threadIdx.x & 31;
    if (w >= NN) return;
    float4 xv = ((const float4*)x)[w*32 + l];
    float p0 = d4(xv, ((const float4*)g_vvec[0])[l]);
    float p1 = d4(xv, ((const float4*)g_vvec[3])[l]);
    float p2 = d4(xv, ((const float4*)g_vvec[1])[l]);
    float p3 = d4(xv, ((const float4*)g_vvec[4])[l]);
    p0 = wredsum(p0); p1 = wredsum(p1); p2 = wredsum(p2); p3 = wredsum(p3);
    if (l == 0){
        g_ss1[w] = make_float2(p0, p1);
        g_sd1[w] = make_float2(p2, p3);
    }
}

__global__ void k_scatter(const int* __restrict__ el, const int* __restrict__ et,
                          const int* __restrict__ eln, const int* __restrict__ etn){
    int i = blockIdx.x*256 + threadIdx.x;
    if (i >= NET) return;
    int n, e1, ta, tb;
    if (i < NE){
        n = __ldcs(el + i); e1 = __ldcs(el + NE + i); ta = __ldcs(et + i); tb = -1;
    } else {
        int j = i - NE;
        n = __ldcs(eln + j); e1 = __ldcs(eln + NEN + j);
        ta = __ldcs(etn + 2*j); tb = __ldcs(etn + 2*j + 1);
    }
    int pos = atomicAdd(&g_cur[n], 1);
    g_meta[pos] = make_int4(e1, i, ta, tb);
}

// ---------------- per-node scalar dots layer 2 ----------------
__global__ void k_sdots2(){
    int w = (blockIdx.x*blockDim.x + threadIdx.x) >> 5;
    int l = threadIdx.x & 31;
    if (w >= NN) return;
    float4 xv = ((const float4*)g_x2)[w*32 + l];
    float p0 = d4(xv, ((const float4*)g_w2[0])[l]);
    float p1 = d4(xv, ((const float4*)g_w2[1])[l]);
    p0 = wredsum(p0); p1 = wredsum(p1);
    if (l == 0){ g_s2s[w] = p0; g_s2d[w] = p1; }
}

// ---------------- layer 1 edge pass (CSR, warp per node, x2 unroll, 4 blk/SM) ----------------
__global__ __launch_bounds__(256, 4) void k_edge1(
        const float* __restrict__ x, const float* __restrict__ eemb,
        const float* __restrict__ rel){
    int w = (blockIdx.x*blockDim.x + threadIdx.x) >> 5;
    int l = threadIdx.x & 31;
    if (w >= NN) return;
    int beg = g_rp[w], end = g_rp[w+1];

    const float4* x4 = (const float4*)x;
    const float4* e4 = (const float4*)eemb;
    const float4* r4 = (const float4*)rel;
    float4 vr0 = ((const float4*)g_vvec[2])[l];
    float4 vr1 = ((const float4*)g_vvec[5])[l];
    float2 ssn = g_ss1[w];

    float4 wx0 = {0,0,0,0}, wx1 = {0,0,0,0}, we0 = {0,0,0,0}, we1 = {0,0,0,0};
    float rs0 = 0.f, rs1 = 0.f;

    int p = beg;
    for (; p + 1 < end; p += 2){
        int4 ca = __ldcs(&g_meta[p]);
        int4 cb = __ldcs(&g_meta[p+1]);
        float4 xva = x4[(size_t)ca.x*32 + l];
        float4 xvb = x4[(size_t)cb.x*32 + l];
        float2 sda = g_sd1[ca.x];
        float2 sdb = g_sd1[cb.x];
        bool dira = ca.y < NE, dirb = cb.y < NE;
        float4 eva, evb;
        float sr0a = 0.f, sr1a = 0.f, sr0b = 0.f, sr1b = 0.f;
        float q0a = 0.f, q1a = 0.f, q0b = 0.f, q1b = 0.f;
        if (dira) eva = __ldcs(&e4[(size_t)ca.y*32 + l]);
        else {
            float4 ra = r4[ca.z*32 + l];
            float4 rb = r4[ca.w*32 + l];
            eva = make_float4(ra.x+rb.x, ra.y+rb.y, ra.z+rb.z, ra.w+rb.w);
            float2 sa = *(const float2*)(g_srel1 + ca.z*2);
            float2 sb = *(const float2*)(g_srel1 + ca.w*2);
            sr0a = sa.x + sb.x; sr1a = sa.y + sb.y;
        }
        if (dirb) evb = __ldcs(&e4[(size_t)cb.y*32 + l]);
        else {
            float4 ra = r4[cb.z*32 + l];
            float4 rb = r4[cb.w*32 + l];
            evb = make_float4(ra.x+rb.x, ra.y+rb.y, ra.z+rb.z, ra.w+rb.w);
            float2 sa = *(const float2*)(g_srel1 + cb.z*2);
            float2 sb = *(const float2*)(g_srel1 + cb.w*2);
            sr0b = sa.x + sb.x; sr1b = sa.y + sb.y;
        }
        if (dira){ q0a = d4(eva, vr0); q1a = d4(eva, vr1); }
        if (dirb){ q0b = d4(evb, vr0); q1b = d4(evb, vr1); }
        #pragma unroll
        for (int o = 16; o; o >>= 1){
            q0a += __shfl_xor_sync(0xFFFFFFFFu, q0a, o);
            q1a += __shfl_xor_sync(0xFFFFFFFFu, q1a, o);
            q0b += __shfl_xor_sync(0xFFFFFFFFu, q0b, o);
            q1b += __shfl_xor_sync(0xFFFFFFFFu, q1b, o);
        }
        if (dira){ sr0a = q0a; sr1a = q1a; }
        if (dirb){ sr0b = q0b; sr1b = q1b; }
        float ee0a = __expf(-lrelu(ssn.x + sda.x + sr0a));
        float ee1a = __expf(-lrelu(ssn.y + sda.y + sr1a));
        float ee0b = __expf(-lrelu(ssn.x + sdb.x + sr0b));
        float ee1b = __expf(-lrelu(ssn.y + sdb.y + sr1b));
        rs0 += ee0a + ee0b; rs1 += ee1a + ee1b;
        fma4(wx0, ee0a, xva); fma4(wx0, ee0b, xvb);
        fma4(wx1, ee1a, xva); fma4(wx1, ee1b, xvb);
        fma4(we0, ee0a, eva); fma4(we0, ee0b, evb);
        fma4(we1, ee1a, eva); fma4(we1, ee1b, evb);
    }
    if (p < end){
        int4 ca = __ldcs(&g_meta[p]);
        float4 xva = x4[(size_t)ca.x*32 + l];
        float2 sda = g_sd1[ca.x];
        float4 eva;
        float sr0a, sr1a;
        if (ca.y < NE){
            eva = __ldcs(&e4[(size_t)ca.y*32 + l]);
            float q0 = d4(eva, vr0), q1 = d4(eva, vr1);
            #pragma unroll
            for (int o = 16; o; o >>= 1){
                q0 += __shfl_xor_sync(0xFFFFFFFFu, q0, o);
                q1 += __shfl_xor_sync(0xFFFFFFFFu, q1, o);
            }
            sr0a = q0; sr1a = q1;
        } else {
            float4 ra = r4[ca.z*32 + l];
            float4 rb = r4[ca.w*32 + l];
            eva = make_float4(ra.x+rb.x, ra.y+rb.y, ra.z+rb.z, ra.w+rb.w);
            float2 sa = *(const float2*)(g_srel1 + ca.z*2);
            float2 sb = *(const float2*)(g_srel1 + ca.w*2);
            sr0a = sa.x + sb.x; sr1a = sa.y + sb.y;
        }
        float ee0 = __expf(-lrelu(ssn.x + sda.x + sr0a));
        float ee1 = __expf(-lrelu(ssn.y + sda.y + sr1a));
        rs0 += ee0; rs1 += ee1;
        fma4(wx0, ee0, xva); fma4(wx1, ee1, xva);
        fma4(we0, ee0, eva); fma4(we1, ee1, eva);
    }

    float i0 = (end > beg) ? (1.f / rs0) : 0.f;
    float i1 = (end > beg) ? (1.f / rs1) : 0.f;
    float4* c4 = (float4*)g_cat1;
    size_t b = (size_t)w*128;
    __stcs(&c4[b +  0 + l], make_float4(wx0.x*i0, wx0.y*i0, wx0.z*i0, wx0.w*i0));
    __stcs(&c4[b + 32 + l], make_float4(we0.x*i0, we0.y*i0, we0.z*i0, we0.w*i0));
    __stcs(&c4[b + 64 + l], make_float4(wx1.x*i1, wx1.y*i1, wx1.z*i1, wx1.w*i1));
    __stcs(&c4[b + 96 + l], make_float4(we1.x*i1, we1.y*i1, we1.z*i1, we1.w*i1));
}

// ---------------- layer 2 edge pass (x2 unroll, 4 blk/SM) ----------------
__global__ __launch_bounds__(256, 4) void k_edge2(){
    int w = (blockIdx.x*blockDim.x + threadIdx.x) >> 5;
    int l = threadIdx.x & 31;
    if (w >= NN) return;
    int beg = g_rp[w], end = g_rp[w+1];

    const float4* x4 = (const float4*)g_x2;
    const float4* o4 = (const float4*)g_outrel;
    float ssn = g_s2s[w];

    float4 wx = {0,0,0,0}, wo = {0,0,0,0}, sx = {0,0,0,0}, so = {0,0,0,0};
    float rs = 0.f;

    int p = beg;
    for (; p + 1 < end; p += 2){
        int4 ca = __ldcs(&g_meta[p]);
        int4 cb = __ldcs(&g_meta[p+1]);
        float4 xva = x4[(size_t)ca.x*32 + l];
        float4 xvb = x4[(size_t)cb.x*32 + l];
        float sda = g_s2d[ca.x];
        float sdb = g_s2d[cb.x];
        float4 ova, ovb;
        float sra, srb;
        if (ca.w < 0){ ova = o4[ca.z*32 + l]; sra = g_s2rel[ca.z]; }
        else {
            float4 ra = o4[ca.z*32 + l], rb = o4[ca.w*32 + l];
            ova = make_float4(ra.x+rb.x, ra.y+rb.y, ra.z+rb.z, ra.w+rb.w);
            sra = g_s2rel[ca.z] + g_s2rel[ca.w];
        }
        if (cb.w < 0){ ovb = o4[cb.z*32 + l]; srb = g_s2rel[cb.z]; }
        else {
            float4 ra = o4[cb.z*32 + l], rb = o4[cb.w*32 + l];
            ovb = make_float4(ra.x+rb.x, ra.y+rb.y, ra.z+rb.z, ra.w+rb.w);
            srb = g_s2rel[cb.z] + g_s2rel[cb.w];
        }
        float eea = __expf(-lrelu(ssn + sda + sra));
        float eeb = __expf(-lrelu(ssn + sdb + srb));
        rs += eea + eeb;
        fma4(wx, eea, xva); fma4(wx, eeb, xvb);
        fma4(wo, eea, ova); fma4(wo, eeb, ovb);
        sx.x += xva.x + xvb.x; sx.y += xva.y + xvb.y;
        sx.z += xva.z + xvb.z; sx.w += xva.w + xvb.w;
        so.x += ova.x + ovb.x; so.y += ova.y + ovb.y;
        so.z += ova.z + ovb.z; so.w += ova.w + ovb.w;
    }
    if (p < end){
        int4 ca = __ldcs(&g_meta[p]);
        float4 xva = x4[(size_t)ca.x*32 + l];
        float sda = g_s2d[ca.x];
        float4 ova; float sra;
        if (ca.w < 0){ ova = o4[ca.z*32 + l]; sra = g_s2rel[ca.z]; }
        else {
            float4 ra = o4[ca.z*32 + l], rb = o4[ca.w*32 + l];
            ova = make_float4(ra.x+rb.x, ra.y+rb.y, ra.z+rb.z, ra.w+rb.w);
            sra = g_s2rel[ca.z] + g_s2rel[ca.w];
        }
        float eea = __expf(-lrelu(ssn + sda + sra));
        rs += eea;
        fma4(wx, eea, xva); fma4(wo, eea, ova);
        sx.x += xva.x; sx.y += xva.y; sx.z += xva.z; sx.w += xva.w;
        so.x += ova.x; so.y += ova.y; so.z += ova.z; so.w += ova.w;
    }

    int cnt = end - beg;
    float ic = cnt ? (1.f / (float)cnt) : 0.f;
    float4* a4 = (float4*)g_acc2;
    size_t b = (size_t)w*128;
    __stcs(&a4[b +  0 + l], wx);
    __stcs(&a4[b + 32 + l], wo);
    __stcs(&a4[b + 64 + l], make_float4(sx.x*ic, sx.y*ic, sx.z*ic, sx.w*ic));
    __stcs(&a4[b + 96 + l], make_float4(so.x*ic, so.y*ic, so.z*ic, so.w*ic));
    if (l == 0) g_rs2[w] = rs;
}

// ---------------- layer-1 GEMM (register-pipelined): x2 = elu([x | cat1_h] @ Ah^T) ----------------
__global__ __launch_bounds__(256, 2) void k_tgemm1(const float* __restrict__ Aext){
    const int h = blockIdx.y;
    const float* A1 = Aext;                    // x, lda 128
    const float* A2 = g_cat1 + h*256;          // lda 512
    const __nv_bfloat16* Bh = g_Bh1 + h*24576;
    const __nv_bfloat16* Bl = g_Bl1 + h*24576;
    const int K1 = 128, K = 384, M = NN;
    constexpr int BN = 64, NF = BN/16;

    __shared__ __align__(16) __nv_bfloat16 Ah[128][40];
    __shared__ __align__(16) __nv_bfloat16 Al[128][40];
    __shared__ __align__(16) __nv_bfloat16 Bhs[BN][40];
    __shared__ __align__(16) __nv_bfloat16 Bls[BN][40];

    int tid = threadIdx.x, lane = tid & 31, warp = tid >> 5;
    int wm = (warp & 3) * 32;
    int wn = (warp >> 2) * (BN/2);
    int bm0 = blockIdx.x * 128;

    float d[2][NF][4];
    #pragma unroll
    for (int f = 0; f < 2; f++)
        #pragma unroll
        for (int j = 0; j < NF; j++)
            #pragma unroll
            for (int q = 0; q < 4; q++) d[f][j][q] = 0.f;

    int ar = tid >> 1, akq = (tid & 1) * 16;
    int bn = tid / 4, bkq = (tid % 4) * 8;
    int m = bm0 + ar;
    bool mv = m < M;

    float4 areg[4];
    uint4 bh_r, bl_r;
    auto ldA = [&](int kc){
        if (kc < K1){
            const float* a = A1 + (size_t)m*128 + kc + akq;
            #pragma unroll
            for (int j = 0; j < 4; j++)
                areg[j] = mv ? *(const float4*)(a + 4*j) : make_float4(0,0,0,0);
        } else {
            const float* a = A2 + (size_t)m*512 + (kc - K1) + akq;
            #pragma unroll
            for (int j = 0; j < 4; j++)
                areg[j] = mv ? __ldcs((const float4*)(a + 4*j)) : make_float4(0,0,0,0);
        }
    };
    ldA(0);
    bh_r = *(const uint4*)(Bh + (size_t)bn*384 + bkq);
    bl_r = *(const uint4*)(Bl + (size_t)bn*384 + bkq);

    for (int k0 = 0; k0 < K; k0 += 32){
        #pragma unroll
        for (int j = 0; j < 4; j++)
            cvt_store_row(&Ah[ar][akq + 4*j], &Al[ar][akq + 4*j], areg[j]);
        *(uint4*)&Bhs[bn][bkq] = bh_r;
        *(uint4*)&Bls[bn][bkq] = bl_r;
        __syncthreads();

        int kn = k0 + 32;
        if (kn < K){
            ldA(kn);
            bh_r = *(const uint4*)(Bh + (size_t)bn*384 + kn + bkq);
            bl_r = *(const uint4*)(Bl + (size_t)bn*384 + kn + bkq);
        }

        #pragma unroll
        for (int kk = 0; kk < 32; kk += 16){
            unsigned ah_[2][4], al_[2][4], bh_[NF][2], bl_[NF][2];
            #pragma unroll
            for (int f = 0; f < 2; f++){
                int rrow = wm + f*16 + (lane & 15);
                int rcol = kk + (lane >> 4) * 8;
                ldsm4(ah_[f][0], ah_[f][1], ah_[f][2], ah_[f][3], smem_u32(&Ah[rrow][rcol]));
                ldsm4(al_[f][0], al_[f][1], al_[f][2], al_[f][3], smem_u32(&Al[rrow][rcol]));
            }
            #pragma unroll
            for (int g = 0; g < NF/2; g++){
                int nb = wn + g*16 + ((lane >> 4) << 3) + (lane & 7);
                int kc = kk + ((lane >> 3) & 1) * 8;
                ldsm4(bh_[2*g][0], bh_[2*g][1], bh_[2*g+1][0], bh_[2*g+1][1], smem_u32(&Bhs[nb][kc]));
                ldsm4(bl_[2*g][0], bl_[2*g][1], bl_[2*g+1][0], bl_[2*g+1][1], smem_u32(&Bls[nb][kc]));
            }
            #pragma unroll
            for (int f = 0; f < 2; f++)
                #pragma unroll
                for (int j = 0; j < NF; j++){
                    mmabf(d[f][j], ah_[f], bh_[j]);
                    mmabf(d[f][j], ah_[f], bl_[j]);
                    mmabf(d[f][j], al_[f], bh_[j]);
                }
        }
        __syncthreads();
    }

    int gid = lane >> 2, tig = lane & 3;
    #pragma unroll
    for (int f = 0; f < 2; f++){
        #pragma unroll
        for (int j = 0; j < NF; j++){
            int col = h*64 + wn + j*8 + tig*2;
            int m0r = bm0 + wm + f*16 + gid;
            #pragma unroll
            for (int half = 0; half < 2; half++){
                int mm = m0r + half*8;
                if (mm >= M) continue;
                bool live = (g_rp[mm+1] - g_rp[mm]) > 0;
                float v0 = live ? eluf(d[f][j][half*2+0]) : 0.f;
                float v1 = live ? eluf(d[f][j][half*2+1]) : 0.f;
                *(float2*)&g_x2[(size_t)mm*128 + col] = make_float2(v0, v1);
            }
        }
    }
}

// ---------------- layer-2 fused GEMM (A register-pipelined): hn/un, direct out ----------------
__global__ __launch_bounds__(256) void k_tgemm2(float* __restrict__ out){
    const int which = blockIdx.y;
    const float* A2 = g_acc2 + (which ? 256 : 0);
    const int K1 = 128, K = 384, M = NN;
    constexpr int BN = 128, NF = BN/16;

    __shared__ __align__(16) __nv_bfloat16 Ah[128][40];
    __shared__ __align__(16) __nv_bfloat16 Al[128][40];
    __shared__ __align__(16) __nv_bfloat16 Bhs[BN][40];
    __shared__ __align__(16) __nv_bfloat16 Bls[BN][40];

    int tid = threadIdx.x, lane = tid & 31, warp = tid >> 5;
    int wm = (warp & 3) * 32;
    int wn = (warp >> 2) * 64;
    int bm0 = blockIdx.x * 128;

    float d[2][NF][4];
    #pragma unroll
    for (int f = 0; f < 2; f++)
        #pragma unroll
        for (int j = 0; j < NF; j++)
            #pragma unroll
            for (int q = 0; q < 4; q++) d[f][j][q] = 0.f;

    int ar = tid >> 1, akq = (tid & 1) * 16;
    int bn = tid / 2, bkq = (tid & 1) * 16;
    int m = bm0 + ar;
    bool mv = m < M;
    float scl = 1.f;
    if (which == 0 && mv) scl = g_rs2[m];   // hn: rs-scaled x2 rows

    float4 areg[4];
    float sreg = scl;
    auto ldA = [&](int kc){
        if (kc < K1){
            const float* a = g_x2 + (size_t)m*128 + kc + akq;
            #pragma unroll
            for (int j = 0; j < 4; j++)
                areg[j] = mv ? *(const float4*)(a + 4*j) : make_float4(0,0,0,0);
            sreg = scl;
        } else {
            const float* a = A2 + (size_t)m*512 + (kc - K1) + akq;
            #pragma unroll
            for (int j = 0; j < 4; j++)
                areg[j] = mv ? __ldcs((const float4*)(a + 4*j)) : make_float4(0,0,0,0);
            sreg = 1.f;
        }
    };
    ldA(0);

    for (int k0 = 0; k0 < K; k0 += 32){
        float s = sreg;
        #pragma unroll
        for (int j = 0; j < 4; j++){
            float4 v = areg[j];
            v.x *= s; v.y *= s; v.z *= s; v.w *= s;
            cvt_store_row(&Ah[ar][akq + 4*j], &Al[ar][akq + 4*j], v);
        }
        #pragma unroll
        for (int j = 0; j < 16; j += 8){
            *(uint4*)&Bhs[bn][bkq+j] = *(const uint4*)(g_Bh2 + (size_t)bn*384 + k0 + bkq + j);
            *(uint4*)&Bls[bn][bkq+j] = *(const uint4*)(g_Bl2 + (size_t)bn*384 + k0 + bkq + j);
        }
        __syncthreads();

        int kn = k0 + 32;
        if (kn < K) ldA(kn);

        #pragma unroll
        for (int kk = 0; kk < 32; kk += 16){
            unsigned ah_[2][4], al_[2][4], bh_[NF][2], bl_[NF][2];
            #pragma unroll
            for (int f = 0; f < 2; f++){
                int rrow = wm + f*16 + (lane & 15);
                int rcol = kk + (lane >> 4) * 8;
                ldsm4(ah_[f][0], ah_[f][1], ah_[f][2], ah_[f][3], smem_u32(&Ah[rrow][rcol]));
                ldsm4(al_[f][0], al_[f][1], al_[f][2], al_[f][3], smem_u32(&Al[rrow][rcol]));
            }
            #pragma unroll
            for (int g = 0; g < NF/2; g++){
                int nb = wn + g*16 + ((lane >> 4) << 3) + (lane & 7);
                int kc = kk + ((lane >> 3) & 1) * 8;
                ldsm4(bh_[2*g][0], bh_[2*g][1], bh_[2*g+1][0], bh_[2*g+1][1], smem_u32(&Bhs[nb][kc]));
                ldsm4(bl_[2*g][0], bl_[2*g][1], bl_[2*g+1][0], bl_[2*g+1][1], smem_u32(&Bls[nb][kc]));
            }
            #pragma unroll
            for (int f = 0; f < 2; f++)
                #pragma unroll
                for (int j = 0; j < NF; j++){
                    mmabf(d[f][j], ah_[f], bh_[j]);
                    mmabf(d[f][j], ah_[f], bl_[j]);
                    mmabf(d[f][j], al_[f], bh_[j]);
                }
        }
        __syncthreads();
    }

    // fused epilogue -> d_out
    int gid = lane >> 2, tig = lane & 3;
    #pragma unroll
    for (int f = 0; f < 2; f++){
        #pragma unroll
        for (int half = 0; half < 2; half++){
            int mm = bm0 + wm + f*16 + gid + half*8;
            if (mm >= M) continue;
            float inv = 0.f;
            if (which == 0){
                float rs = g_rs2[mm];
                inv = (rs > 0.f) ? (1.f / rs) : 0.f;
            }
            #pragma unroll
            for (int j = 0; j < NF; j++){
                int col = wn + j*8 + tig*2;
                float v0 = d[f][j][half*2+0];
                float v1 = d[f][j][half*2+1];
                size_t o = (size_t)mm*128 + col;
                if (which == 0){
                    __stcs((float2*)&out[o],        make_float2(eluf(v0*inv), eluf(v1*inv)));
                    __stcs((float2*)&out[OFF2 + o], make_float2(eluf(v0),     eluf(v1)));
                } else {
                    __stcs((float2*)&out[OFF3 + o], make_float2(eluf(v0), eluf(v1)));
                }
            }
        }
    }
}

// ---------------- launcher ----------------
extern "C" void kernel_launch(void* const* d_in, const int* in_sizes, int n_in,
                              void* d_out, int out_size){
    const float* x    = (const float*)d_in[0];
    const float* rel  = (const float*)d_in[1];
    const float* eemb = (const float*)d_in[2];
    const float* ah   = (const float*)d_in[3];
    const float* a2h  = (const float*)d_in[4];
    const float* W    = (const float*)d_in[5];
    const float* ao   = (const float*)d_in[6];
    const float* a2o  = (const float*)d_in[7];
    const int* el  = (const int*)d_in[8];
    const int* et  = (const int*)d_in[9];
    const int* eln = (const int*)d_in[10];
    const int* etn = (const int*)d_in[11];
    float* out = (float*)d_out;

    const int GB = (NN + 127) / 128;   // 391

    // fused setup: hist + weight prep (independent work, one launch)
    k_setup1<<<HIST_BLKS + PREP_BLKS, 256>>>(el, eln, ah, a2h, ao, a2o, rel, W, out);
    // fused: scan + srel + sdots1 (all depend only on setup1)
    k_setup2<<<7 + 6250, 256>>>(x, rel);
    k_scatter<<<HIST_BLKS, 256>>>(el, et, eln, etn);

    // layer 1  (k_edge1 stays in the ncu capture slot)
    k_edge1<<<6250, 256>>>(x, eemb, rel);
    k_tgemm1<<<dim3(GB, 2), 256>>>(x);

    // layer 2
    k_sdots2<<<6250, 256>>>();
    k_edge2<<<6250, 256>>>();
    k_tgemm2<<<dim3(GB, 2), 256>>>(out);
}

// round 14
// speedup vs baseline: 1.0365x; 1.0365x over previous
#include <cuda_runtime.h>
#include <cuda_bf16.h>
#include <math.h>

#define NN 50000
#define NFEAT 128
#define RDIM 128
#define NREL 500
#define NE 800000
#define NEN 100000
#define NET 900000
#define DOUT 128
#define ALPHA 0.2f

// output section offsets (floats)
#define OFF1 (NN*DOUT)            /* out_rel */
#define OFF2 (OFF1 + NREL*DOUT)   /* elu(h_num2) */
#define OFF3 (OFF2 + NN*DOUT)     /* elu(h_unif2) */

// ---------------- scratch (device globals; no allocation allowed) ----------------
static __device__ int  g_cnt[NN];          // zero-init at load; re-zeroed by k_setup2 each run
static __device__ int  g_rp[NN+1];
static __device__ int  g_cur[NN];
static __device__ int4 g_meta[NET];                       // (e1, idx, ta, tb)
static __device__ __align__(16) float2 g_ss1[NN];
static __device__ __align__(16) float2 g_sd1[NN];
static __device__ __align__(16) float g_cat1[(size_t)NN*512];   // [n][h][wx(128) we(128)]
static __device__ __align__(16) float g_x2[(size_t)NN*128];
static __device__ float g_s2s[NN], g_s2d[NN];
static __device__ __align__(16) float g_acc2[(size_t)NN*512];   // [n][wx wo sx/c so/c]
static __device__ float g_rs2[NN];
static __device__ __align__(16) float g_vvec[6][128];     // [h*3+w], w: 0=src 1=dst 2=rel
static __device__ __align__(8)  float g_srel1[2*NREL];    // [t*2+h]
static __device__ __align__(16) float g_w2[3][128];
static __device__ float g_s2rel[NREL];
static __device__ __align__(16) float g_outrel[NREL*128];
// bf16 hi/lo weights in ORIGINAL [o][k] layout (k contiguous)
static __device__ __align__(16) __nv_bfloat16 g_Bh1[2*64*384];
static __device__ __align__(16) __nv_bfloat16 g_Bl1[2*64*384];
static __device__ __align__(16) __nv_bfloat16 g_Bh2[128*384];
static __device__ __align__(16) __nv_bfloat16 g_Bl2[128*384];

// ---------------- helpers ----------------
__device__ __forceinline__ float lrelu(float z){ return z > 0.f ? z : ALPHA*z; }
__device__ __forceinline__ float eluf(float z){ return z > 0.f ? z : (__expf(z) - 1.f); }
__device__ __forceinline__ float d4(float4 a, float4 b){
    return a.x*b.x + a.y*b.y + a.z*b.z + a.w*b.w;
}
__device__ __forceinline__ float wredsum(float v){
    #pragma unroll
    for (int o = 16; o; o >>= 1) v += __shfl_xor_sync(0xFFFFFFFFu, v, o);
    return v;
}
__device__ __forceinline__ void fma4(float4 &acc, float s, float4 v){
    acc.x += s*v.x; acc.y += s*v.y; acc.z += s*v.z; acc.w += s*v.w;
}
__device__ __forceinline__ unsigned smem_u32(const void* p){
    return (unsigned)__cvta_generic_to_shared(p);
}
__device__ __forceinline__ void ldsm4(unsigned &r0, unsigned &r1, unsigned &r2, unsigned &r3, unsigned a){
    asm volatile("ldmatrix.sync.aligned.m8n8.x4.shared.b16 {%0,%1,%2,%3},[%4];"
        : "=r"(r0),"=r"(r1),"=r"(r2),"=r"(r3) : "r"(a));
}
__device__ __forceinline__ void mmabf(float* d, const unsigned* a, const unsigned* b){
    asm volatile("mma.sync.aligned.m16n8k16.row.col.f32.bf16.bf16.f32 "
        "{%0,%1,%2,%3},{%4,%5,%6,%7},{%8,%9},{%0,%1,%2,%3};"
        : "+f"(d[0]),"+f"(d[1]),"+f"(d[2]),"+f"(d[3])
        : "r"(a[0]),"r"(a[1]),"r"(a[2]),"r"(a[3]),"r"(b[0]),"r"(b[1]));
}
__device__ __forceinline__ void cvt_store_row(__nv_bfloat16* dh, __nv_bfloat16* dl, float4 v){
    __nv_bfloat162 h0 = __floats2bfloat162_rn(v.x, v.y);
    __nv_bfloat162 h1 = __floats2bfloat162_rn(v.z, v.w);
    __nv_bfloat162 l0 = __floats2bfloat162_rn(v.x - __low2float(h0),
                                              v.y - __high2float(h0));
    __nv_bfloat162 l1 = __floats2bfloat162_rn(v.z - __low2float(h1),
                                              v.w - __high2float(h1));
    *(__nv_bfloat162*)(dh)     = h0;
    *(__nv_bfloat162*)(dh + 2) = h1;
    *(__nv_bfloat162*)(dl)     = l0;
    *(__nv_bfloat162*)(dl + 2) = l1;
}

// ---------------- fused setup 1: hist + weight split/fold + out_rel ----------------
#define HIST_BLKS ((NET + 255)/256)                 // 3516
#define PREP_TOT (99456 + NREL*128)                 // 163456
#define PREP_BLKS ((PREP_TOT + 255)/256)            // 639
__global__ void k_setup1(const int* __restrict__ el, const int* __restrict__ eln,
                         const float* __restrict__ ah, const float* __restrict__ a2h,
                         const float* __restrict__ ao, const float* __restrict__ a2o,
                         const float* __restrict__ rel, const float* __restrict__ W,
                         float* __restrict__ out){
    if (blockIdx.x < HIST_BLKS){
        int i = blockIdx.x*256 + threadIdx.x;
        if (i >= NET) return;
        int n = (i < NE) ? __ldcs(el + i) : __ldcs(eln + i - NE);
        atomicAdd(&g_cnt[n], 1);
        return;
    }
    int id = (blockIdx.x - HIST_BLKS)*256 + threadIdx.x;
    if (id < 49152){
        float v = ah[id];
        __nv_bfloat16 h = __float2bfloat16(v);
        g_Bh1[id] = h;
        g_Bl1[id] = __float2bfloat16(v - __bfloat162float(h));
    } else if (id < 98304){
        int j = id - 49152;
        float v = ao[j];
        __nv_bfloat16 h = __float2bfloat16(v);
        g_Bh2[j] = h;
        g_Bl2[j] = __float2bfloat16(v - __bfloat162float(h));
    } else if (id < 99072){
        int j = id - 98304;
        int m = j / 128, k = j % 128;
        int h = m / 3, w = m % 3;
        float s = 0.f;
        #pragma unroll 4
        for (int o = 0; o < 64; o++)
            s += a2h[h*64 + o] * ah[h*24576 + o*384 + w*128 + k];
        g_vvec[m][k] = s;
    } else if (id < 99456){
        int j = id - 99072;
        int m = j / 128, k = j % 128;
        float s = 0.f;
        #pragma unroll 4
        for (int o = 0; o < 128; o++)
            s += a2o[o] * ao[o*384 + m*128 + k];
        g_w2[m][k] = s;
    } else if (id < PREP_TOT){
        int j = id - 99456;                    // out_rel = rel @ W
        int t = j / 128, o = j % 128;
        float s = 0.f;
        #pragma unroll 4
        for (int k = 0; k < 128; k++) s += rel[t*128 + k] * W[k*128 + o];
        g_outrel[j] = s;
        out[OFF1 + j] = s;
    }
}

// ---------------- fused setup 2: scan + srel + sdots1 ----------------
__global__ void k_setup2(const float* __restrict__ x, const float* __restrict__ rel){
    if (blockIdx.x == 0){
        __shared__ int sp[256];
        int t = threadIdx.x;
        const int C = (NN + 255) / 256;   // 196
        int base = t * C;
        int s = 0;
        for (int i = 0; i < C; i++){ int idx = base + i; if (idx < NN) s += g_cnt[idx]; }
        sp[t] = s; __syncthreads();
        for (int off = 1; off < 256; off <<= 1){
            int v = (t >= off) ? sp[t - off] : 0;
            __syncthreads();
            sp[t] += v;
            __syncthreads();
        }
        int pre = (t == 0) ? 0 : sp[t-1];
        for (int i = 0; i < C; i++){
            int idx = base + i;
            if (idx < NN){
                int c = g_cnt[idx];
                g_rp[idx] = pre; g_cur[idx] = pre; pre += c;
                g_cnt[idx] = 0;                    // self-clean for next run
            }
        }
        if (t == 255) g_rp[NN] = NET;
        return;
    }
    if (blockIdx.x <= 6){
        int id = (blockIdx.x - 1)*256 + threadIdx.x;
        if (id < 1000){
            int t = id >> 1, h = id & 1;
            const float* v = g_vvec[h*3 + 2];
            float s = 0.f;
            #pragma unroll 4
            for (int k = 0; k < 128; k++) s += rel[t*128 + k] * v[k];
            g_srel1[id] = s;
        } else if (id < 1500){
            int t = id - 1000;
            float s = 0.f;
            #pragma unroll 4
            for (int k = 0; k < 128; k++) s += g_outrel[t*128 + k] * g_w2[2][k];
            g_s2rel[t] = s;
        }
        return;
    }
    int w = (blockIdx.x - 7)*8 + (threadIdx.x >> 5);
    int l = threadIdx.x & 31;
    if (w >= NN) return;
    float4 xv = ((const float4*)x)[w*32 + l];
    float p0 = d4(xv, ((const float4*)g_vvec[0])[l]);
    float p1 = d4(xv, ((const float4*)g_vvec[3])[l]);
    float p2 = d4(xv, ((const float4*)g_vvec[1])[l]);
    float p3 = d4(xv, ((const float4*)g_vvec[4])[l]);
    p0 = wredsum(p0); p1 = wredsum(p1); p2 = wredsum(p2); p3 = wredsum(p3);
    if (l == 0){
        g_ss1[w] = make_float2(p0, p1);
        g_sd1[w] = make_float2(p2, p3);
    }
}

__global__ void k_scatter(const int* __restrict__ el, const int* __restrict__ et,
                          const int* __restrict__ eln, const int* __restrict__ etn){
    int i = blockIdx.x*256 + threadIdx.x;
    if (i >= NET) return;
    int n, e1, ta, tb;
    if (i < NE){
        n = __ldcs(el + i); e1 = __ldcs(el + NE + i); ta = __ldcs(et + i); tb = -1;
    } else {
        int j = i - NE;
        n = __ldcs(eln + j); e1 = __ldcs(eln + NEN + j);
        ta = __ldcs(etn + 2*j); tb = __ldcs(etn + 2*j + 1);
    }
    int pos = atomicAdd(&g_cur[n], 1);
    g_meta[pos] = make_int4(e1, i, ta, tb);
}

// ---------------- per-node scalar dots layer 2 ----------------
__global__ void k_sdots2(){
    int w = (blockIdx.x*blockDim.x + threadIdx.x) >> 5;
    int l = threadIdx.x & 31;
    if (w >= NN) return;
    float4 xv = ((const float4*)g_x2)[w*32 + l];
    float p0 = d4(xv, ((const float4*)g_w2[0])[l]);
    float p1 = d4(xv, ((const float4*)g_w2[1])[l]);
    p0 = wredsum(p0); p1 = wredsum(p1);
    if (l == 0){ g_s2s[w] = p0; g_s2d[w] = p1; }
}

// ---------------- layer 1 edge pass: smem-staged meta, x2 unroll, 4 blk/SM ----------------
__global__ __launch_bounds__(256, 4) void k_edge1(
        const float* __restrict__ x, const float* __restrict__ eemb,
        const float* __restrict__ rel){
    __shared__ int4 smeta[8][32];
    int w = (blockIdx.x*blockDim.x + threadIdx.x) >> 5;
    int wl = threadIdx.x >> 5;
    int l = threadIdx.x & 31;
    if (w >= NN) return;
    int beg = g_rp[w], end = g_rp[w+1];

    const float4* x4 = (const float4*)x;
    const float4* e4 = (const float4*)eemb;
    const float4* r4 = (const float4*)rel;
    float4 vr0 = ((const float4*)g_vvec[2])[l];
    float4 vr1 = ((const float4*)g_vvec[5])[l];
    float2 ssn = g_ss1[w];

    float4 wx0 = {0,0,0,0}, wx1 = {0,0,0,0}, we0 = {0,0,0,0}, we1 = {0,0,0,0};
    float rs0 = 0.f, rs1 = 0.f;

    int base = beg;
    int cnt = min(32, end - base);
    int4 pre = make_int4(0,0,0,0);
    if (cnt > 0 && l < cnt) pre = __ldcs(&g_meta[base + l]);   // coalesced 512B stage

    while (base < end){
        smeta[wl][l] = pre;
        __syncwarp();
        int nbase = base + 32;
        if (nbase < end){
            int ncnt = min(32, end - nbase);
            if (l < ncnt) pre = __ldcs(&g_meta[nbase + l]);    // prefetch next block
        }
        int j = 0;
        for (; j + 1 < cnt; j += 2){
            int4 ca = smeta[wl][j];
            int4 cb = smeta[wl][j+1];
            float4 xva = x4[(size_t)ca.x*32 + l];
            float4 xvb = x4[(size_t)cb.x*32 + l];
            float2 sda = g_sd1[ca.x];
            float2 sdb = g_sd1[cb.x];
            bool dira = ca.y < NE, dirb = cb.y < NE;
            float4 eva, evb;
            float sr0a = 0.f, sr1a = 0.f, sr0b = 0.f, sr1b = 0.f;
            float q0a = 0.f, q1a = 0.f, q0b = 0.f, q1b = 0.f;
            if (dira) eva = __ldcs(&e4[(size_t)ca.y*32 + l]);
            else {
                float4 ra = r4[ca.z*32 + l];
                float4 rb = r4[ca.w*32 + l];
                eva = make_float4(ra.x+rb.x, ra.y+rb.y, ra.z+rb.z, ra.w+rb.w);
                float2 sa = *(const float2*)(g_srel1 + ca.z*2);
                float2 sb = *(const float2*)(g_srel1 + ca.w*2);
                sr0a = sa.x + sb.x; sr1a = sa.y + sb.y;
            }
            if (dirb) evb = __ldcs(&e4[(size_t)cb.y*32 + l]);
            else {
                float4 ra = r4[cb.z*32 + l];
                float4 rb = r4[cb.w*32 + l];
                evb = make_float4(ra.x+rb.x, ra.y+rb.y, ra.z+rb.z, ra.w+rb.w);
                float2 sa = *(const float2*)(g_srel1 + cb.z*2);
                float2 sb = *(const float2*)(g_srel1 + cb.w*2);
                sr0b = sa.x + sb.x; sr1b = sa.y + sb.y;
            }
            if (dira){ q0a = d4(eva, vr0); q1a = d4(eva, vr1); }
            if (dirb){ q0b = d4(evb, vr0); q1b = d4(evb, vr1); }
            #pragma unroll
            for (int o = 16; o; o >>= 1){
                q0a += __shfl_xor_sync(0xFFFFFFFFu, q0a, o);
                q1a += __shfl_xor_sync(0xFFFFFFFFu, q1a, o);
                q0b += __shfl_xor_sync(0xFFFFFFFFu, q0b, o);
                q1b += __shfl_xor_sync(0xFFFFFFFFu, q1b, o);
            }
            if (dira){ sr0a = q0a; sr1a = q1a; }
            if (dirb){ sr0b = q0b; sr1b = q1b; }
            float ee0a = __expf(-lrelu(ssn.x + sda.x + sr0a));
            float ee1a = __expf(-lrelu(ssn.y + sda.y + sr1a));
            float ee0b = __expf(-lrelu(ssn.x + sdb.x + sr0b));
            float ee1b = __expf(-lrelu(ssn.y + sdb.y + sr1b));
            rs0 += ee0a + ee0b; rs1 += ee1a + ee1b;
            fma4(wx0, ee0a, xva); fma4(wx0, ee0b, xvb);
            fma4(wx1, ee1a, xva); fma4(wx1, ee1b, xvb);
            fma4(we0, ee0a, eva); fma4(we0, ee0b, evb);
            fma4(we1, ee1a, eva); fma4(we1, ee1b, evb);
        }
        if (j < cnt){
            int4 ca = smeta[wl][j];
            float4 xva = x4[(size_t)ca.x*32 + l];
            float2 sda = g_sd1[ca.x];
            float4 eva;
            float sr0a, sr1a;
            if (ca.y < NE){
                eva = __ldcs(&e4[(size_t)ca.y*32 + l]);
                float q0 = d4(eva, vr0), q1 = d4(eva, vr1);
                #pragma unroll
                for (int o = 16; o; o >>= 1){
                    q0 += __shfl_xor_sync(0xFFFFFFFFu, q0, o);
                    q1 += __shfl_xor_sync(0xFFFFFFFFu, q1, o);
                }
                sr0a = q0; sr1a = q1;
            } else {
                float4 ra = r4[ca.z*32 + l];
                float4 rb = r4[ca.w*32 + l];
                eva = make_float4(ra.x+rb.x, ra.y+rb.y, ra.z+rb.z, ra.w+rb.w);
                float2 sa = *(const float2*)(g_srel1 + ca.z*2);
                float2 sb = *(const float2*)(g_srel1 + ca.w*2);
                sr0a = sa.x + sb.x; sr1a = sa.y + sb.y;
            }
            float ee0 = __expf(-lrelu(ssn.x + sda.x + sr0a));
            float ee1 = __expf(-lrelu(ssn.y + sda.y + sr1a));
            rs0 += ee0; rs1 += ee1;
            fma4(wx0, ee0, xva); fma4(wx1, ee1, xva);
            fma4(we0, ee0, eva); fma4(we1, ee1, eva);
        }
        __syncwarp();
        base += 32;
        cnt = min(32, end - base);
    }

    float i0 = (end > beg) ? (1.f / rs0) : 0.f;
    float i1 = (end > beg) ? (1.f / rs1) : 0.f;
    float4* c4 = (float4*)g_cat1;
    size_t b = (size_t)w*128;
    __stcs(&c4[b +  0 + l], make_float4(wx0.x*i0, wx0.y*i0, wx0.z*i0, wx0.w*i0));
    __stcs(&c4[b + 32 + l], make_float4(we0.x*i0, we0.y*i0, we0.z*i0, we0.w*i0));
    __stcs(&c4[b + 64 + l], make_float4(wx1.x*i1, wx1.y*i1, wx1.z*i1, wx1.w*i1));
    __stcs(&c4[b + 96 + l], make_float4(we1.x*i1, we1.y*i1, we1.z*i1, we1.w*i1));
}

// ---------------- layer 2 edge pass: smem-staged meta, x2 unroll, 4 blk/SM ----------------
__global__ __launch_bounds__(256, 4) void k_edge2(){
    __shared__ int4 smeta[8][32];
    int w = (blockIdx.x*blockDim.x + threadIdx.x) >> 5;
    int wl = threadIdx.x >> 5;
    int l = threadIdx.x & 31;
    if (w >= NN) return;
    int beg = g_rp[w], end = g_rp[w+1];

    const float4* x4 = (const float4*)g_x2;
    const float4* o4 = (const float4*)g_outrel;
    float ssn = g_s2s[w];

    float4 wx = {0,0,0,0}, wo = {0,0,0,0}, sx = {0,0,0,0}, so = {0,0,0,0};
    float rs = 0.f;

    int base = beg;
    int cnt = min(32, end - base);
    int4 pre = make_int4(0,0,0,0);
    if (cnt > 0 && l < cnt) pre = __ldcs(&g_meta[base + l]);

    while (base < end){
        smeta[wl][l] = pre;
        __syncwarp();
        int nbase = base + 32;
        if (nbase < end){
            int ncnt = min(32, end - nbase);
            if (l < ncnt) pre = __ldcs(&g_meta[nbase + l]);
        }
        int j = 0;
        for (; j + 1 < cnt; j += 2){
            int4 ca = smeta[wl][j];
            int4 cb = smeta[wl][j+1];
            float4 xva = x4[(size_t)ca.x*32 + l];
            float4 xvb = x4[(size_t)cb.x*32 + l];
            float sda = g_s2d[ca.x];
            float sdb = g_s2d[cb.x];
            float4 ova, ovb;
            float sra, srb;
            if (ca.w < 0){ ova = o4[ca.z*32 + l]; sra = g_s2rel[ca.z]; }
            else {
                float4 ra = o4[ca.z*32 + l], rb = o4[ca.w*32 + l];
                ova = make_float4(ra.x+rb.x, ra.y+rb.y, ra.z+rb.z, ra.w+rb.w);
                sra = g_s2rel[ca.z] + g_s2rel[ca.w];
            }
            if (cb.w < 0){ ovb = o4[cb.z*32 + l]; srb = g_s2rel[cb.z]; }
            else {
                float4 ra = o4[cb.z*32 + l], rb = o4[cb.w*32 + l];
                ovb = make_float4(ra.x+rb.x, ra.y+rb.y, ra.z+rb.z, ra.w+rb.w);
                srb = g_s2rel[cb.z] + g_s2rel[cb.w];
            }
            float eea = __expf(-lrelu(ssn + sda + sra));
            float eeb = __expf(-lrelu(ssn + sdb + srb));
            rs += eea + eeb;
            fma4(wx, eea, xva); fma4(wx, eeb, xvb);
            fma4(wo, eea, ova); fma4(wo, eeb, ovb);
            sx.x += xva.x + xvb.x; sx.y += xva.y + xvb.y;
            sx.z += xva.z + xvb.z; sx.w += xva.w + xvb.w;
            so.x += ova.x + ovb.x; so.y += ova.y + ovb.y;
            so.z += ova.z + ovb.z; so.w += ova.w + ovb.w;
        }
        if (j < cnt){
            int4 ca = smeta[wl][j];
            float4 xva = x4[(size_t)ca.x*32 + l];
            float sda = g_s2d[ca.x];
            float4 ova; float sra;
            if (ca.w < 0){ ova = o4[ca.z*32 + l]; sra = g_s2rel[ca.z]; }
            else {
                float4 ra = o4[ca.z*32 + l], rb = o4[ca.w*32 + l];
                ova = make_float4(ra.x+rb.x, ra.y+rb.y, ra.z+rb.z, ra.w+rb.w);
                sra = g_s2rel[ca.z] + g_s2rel[ca.w];
            }
            float eea = __expf(-lrelu(ssn + sda + sra));
            rs += eea;
            fma4(wx, eea, xva); fma4(wo, eea, ova);
            sx.x += xva.x; sx.y += xva.y; sx.z += xva.z; sx.w += xva.w;
            so.x += ova.x; so.y += ova.y; so.z += ova.z; so.w += ova.w;
        }
        __syncwarp();
        base += 32;
        cnt = min(32, end - base);
    }

    int ecnt = end - beg;
    float ic = ecnt ? (1.f / (float)ecnt) : 0.f;
    float4* a4 = (float4*)g_acc2;
    size_t b = (size_t)w*128;
    __stcs(&a4[b +  0 + l], wx);
    __stcs(&a4[b + 32 + l], wo);
    __stcs(&a4[b + 64 + l], make_float4(sx.x*ic, sx.y*ic, sx.z*ic, sx.w*ic));
    __stcs(&a4[b + 96 + l], make_float4(so.x*ic, so.y*ic, so.z*ic, so.w*ic));
    if (l == 0) g_rs2[w] = rs;
}

// ---------------- layer-1 GEMM (register-pipelined): x2 = elu([x | cat1_h] @ Ah^T) ----------------
__global__ __launch_bounds__(256, 2) void k_tgemm1(const float* __restrict__ Aext){
    const int h = blockIdx.y;
    const float* A1 = Aext;                    // x, lda 128
    const float* A2 = g_cat1 + h*256;          // lda 512
    const __nv_bfloat16* Bh = g_Bh1 + h*24576;
    const __nv_bfloat16* Bl = g_Bl1 + h*24576;
    const int K1 = 128, K = 384, M = NN;
    constexpr int BN = 64, NF = BN/16;

    __shared__ __align__(16) __nv_bfloat16 Ah[128][40];
    __shared__ __align__(16) __nv_bfloat16 Al[128][40];
    __shared__ __align__(16) __nv_bfloat16 Bhs[BN][40];
    __shared__ __align__(16) __nv_bfloat16 Bls[BN][40];

    int tid = threadIdx.x, lane = tid & 31, warp = tid >> 5;
    int wm = (warp & 3) * 32;
    int wn = (warp >> 2) * (BN/2);
    int bm0 = blockIdx.x * 128;

    float d[2][NF][4];
    #pragma unroll
    for (int f = 0; f < 2; f++)
        #pragma unroll
        for (int j = 0; j < NF; j++)
            #pragma unroll
            for (int q = 0; q < 4; q++) d[f][j][q] = 0.f;

    int ar = tid >> 1, akq = (tid & 1) * 16;
    int bn = tid / 4, bkq = (tid % 4) * 8;
    int m = bm0 + ar;
    bool mv = m < M;

    float4 areg[4];
    uint4 bh_r, bl_r;
    auto ldA = [&](int kc){
        if (kc < K1){
            const float* a = A1 + (size_t)m*128 + kc + akq;
            #pragma unroll
            for (int j = 0; j < 4; j++)
                areg[j] = mv ? *(const float4*)(a + 4*j) : make_float4(0,0,0,0);
        } else {
            const float* a = A2 + (size_t)m*512 + (kc - K1) + akq;
            #pragma unroll
            for (int j = 0; j < 4; j++)
                areg[j] = mv ? __ldcs((const float4*)(a + 4*j)) : make_float4(0,0,0,0);
        }
    };
    ldA(0);
    bh_r = *(const uint4*)(Bh + (size_t)bn*384 + bkq);
    bl_r = *(const uint4*)(Bl + (size_t)bn*384 + bkq);

    for (int k0 = 0; k0 < K; k0 += 32){
        #pragma unroll
        for (int j = 0; j < 4; j++)
            cvt_store_row(&Ah[ar][akq + 4*j], &Al[ar][akq + 4*j], areg[j]);
        *(uint4*)&Bhs[bn][bkq] = bh_r;
        *(uint4*)&Bls[bn][bkq] = bl_r;
        __syncthreads();

        int kn = k0 + 32;
        if (kn < K){
            ldA(kn);
            bh_r = *(const uint4*)(Bh + (size_t)bn*384 + kn + bkq);
            bl_r = *(const uint4*)(Bl + (size_t)bn*384 + kn + bkq);
        }

        #pragma unroll
        for (int kk = 0; kk < 32; kk += 16){
            unsigned ah_[2][4], al_[2][4], bh_[NF][2], bl_[NF][2];
            #pragma unroll
            for (int f = 0; f < 2; f++){
                int rrow = wm + f*16 + (lane & 15);
                int rcol = kk + (lane >> 4) * 8;
                ldsm4(ah_[f][0], ah_[f][1], ah_[f][2], ah_[f][3], smem_u32(&Ah[rrow][rcol]));
                ldsm4(al_[f][0], al_[f][1], al_[f][2], al_[f][3], smem_u32(&Al[rrow][rcol]));
            }
            #pragma unroll
            for (int g = 0; g < NF/2; g++){
                int nb = wn + g*16 + ((lane >> 4) << 3) + (lane & 7);
                int kc = kk + ((lane >> 3) & 1) * 8;
                ldsm4(bh_[2*g][0], bh_[2*g][1], bh_[2*g+1][0], bh_[2*g+1][1], smem_u32(&Bhs[nb][kc]));
                ldsm4(bl_[2*g][0], bl_[2*g][1], bl_[2*g+1][0], bl_[2*g+1][1], smem_u32(&Bls[nb][kc]));
            }
            #pragma unroll
            for (int f = 0; f < 2; f++)
                #pragma unroll
                for (int j = 0; j < NF; j++){
                    mmabf(d[f][j], ah_[f], bh_[j]);
                    mmabf(d[f][j], ah_[f], bl_[j]);
                    mmabf(d[f][j], al_[f], bh_[j]);
                }
        }
        __syncthreads();
    }

    int gid = lane >> 2, tig = lane & 3;
    #pragma unroll
    for (int f = 0; f < 2; f++){
        #pragma unroll
        for (int j = 0; j < NF; j++){
            int col = h*64 + wn + j*8 + tig*2;
            int m0r = bm0 + wm + f*16 + gid;
            #pragma unroll
            for (int half = 0; half < 2; half++){
                int mm = m0r + half*8;
                if (mm >= M) continue;
                bool live = (g_rp[mm+1] - g_rp[mm]) > 0;
                float v0 = live ? eluf(d[f][j][half*2+0]) : 0.f;
                float v1 = live ? eluf(d[f][j][half*2+1]) : 0.f;
                *(float2*)&g_x2[(size_t)mm*128 + col] = make_float2(v0, v1);
            }
        }
    }
}

// ---------------- layer-2 fused GEMM (A register-pipelined): hn/un, direct out ----------------
__global__ __launch_bounds__(256) void k_tgemm2(float* __restrict__ out){
    const int which = blockIdx.y;
    const float* A2 = g_acc2 + (which ? 256 : 0);
    const int K1 = 128, K = 384, M = NN;
    constexpr int BN = 128, NF = BN/16;

    __shared__ __align__(16) __nv_bfloat16 Ah[128][40];
    __shared__ __align__(16) __nv_bfloat16 Al[128][40];
    __shared__ __align__(16) __nv_bfloat16 Bhs[BN][40];
    __shared__ __align__(16) __nv_bfloat16 Bls[BN][40];

    int tid = threadIdx.x, lane = tid & 31, warp = tid >> 5;
    int wm = (warp & 3) * 32;
    int wn = (warp >> 2) * 64;
    int bm0 = blockIdx.x * 128;

    float d[2][NF][4];
    #pragma unroll
    for (int f = 0; f < 2; f++)
        #pragma unroll
        for (int j = 0; j < NF; j++)
            #pragma unroll
            for (int q = 0; q < 4; q++) d[f][j][q] = 0.f;

    int ar = tid >> 1, akq = (tid & 1) * 16;
    int bn = tid / 2, bkq = (tid & 1) * 16;
    int m = bm0 + ar;
    bool mv = m < M;
    float scl = 1.f;
    if (which == 0 && mv) scl = g_rs2[m];   // hn: rs-scaled x2 rows

    float4 areg[4];
    float sreg = scl;
    auto ldA = [&](int kc){
        if (kc < K1){
            const float* a = g_x2 + (size_t)m*128 + kc + akq;
            #pragma unroll
            for (int j = 0; j < 4; j++)
                areg[j] = mv ? *(const float4*)(a + 4*j) : make_float4(0,0,0,0);
            sreg = scl;
        } else {
            const float* a = A2 + (size_t)m*512 + (kc - K1) + akq;
            #pragma unroll
            for (int j = 0; j < 4; j++)
                areg[j] = mv ? __ldcs((const float4*)(a + 4*j)) : make_float4(0,0,0,0);
            sreg = 1.f;
        }
    };
    ldA(0);

    for (int k0 = 0; k0 < K; k0 += 32){
        float s = sreg;
        #pragma unroll
        for (int j = 0; j < 4; j++){
            float4 v = areg[j];
            v.x *= s; v.y *= s; v.z *= s; v.w *= s;
            cvt_store_row(&Ah[ar][akq + 4*j], &Al[ar][akq + 4*j], v);
        }
        #pragma unroll
        for (int j = 0; j < 16; j += 8){
            *(uint4*)&Bhs[bn][bkq+j] = *(const uint4*)(g_Bh2 + (size_t)bn*384 + k0 + bkq + j);
            *(uint4*)&Bls[bn][bkq+j] = *(const uint4*)(g_Bl2 + (size_t)bn*384 + k0 + bkq + j);
        }
        __syncthreads();

        int kn = k0 + 32;
        if (kn < K) ldA(kn);

        #pragma unroll
        for (int kk = 0; kk < 32; kk += 16){
            unsigned ah_[2][4], al_[2][4], bh_[NF][2], bl_[NF][2];
            #pragma unroll
            for (int f = 0; f < 2; f++){
                int rrow = wm + f*16 + (lane & 15);
                int rcol = kk + (lane >> 4) * 8;
                ldsm4(ah_[f][0], ah_[f][1], ah_[f][2], ah_[f][3], smem_u32(&Ah[rrow][rcol]));
                ldsm4(al_[f][0], al_[f][1], al_[f][2], al_[f][3], smem_u32(&Al[rrow][rcol]));
            }
            #pragma unroll
            for (int g = 0; g < NF/2; g++){
                int nb = wn + g*16 + ((lane >> 4) << 3) + (lane & 7);
                int kc = kk + ((lane >> 3) & 1) * 8;
                ldsm4(bh_[2*g][0], bh_[2*g][1], bh_[2*g+1][0], bh_[2*g+1][1], smem_u32(&Bhs[nb][kc]));
                ldsm4(bl_[2*g][0], bl_[2*g][1], bl_[2*g+1][0], bl_[2*g+1][1], smem_u32(&Bls[nb][kc]));
            }
            #pragma unroll
            for (int f = 0; f < 2; f++)
                #pragma unroll
                for (int j = 0; j < NF; j++){
                    mmabf(d[f][j], ah_[f], bh_[j]);
                    mmabf(d[f][j], ah_[f], bl_[j]);
                    mmabf(d[f][j], al_[f], bh_[j]);
                }
        }
        __syncthreads();
    }

    // fused epilogue -> d_out
    int gid = lane >> 2, tig = lane & 3;
    #pragma unroll
    for (int f = 0; f < 2; f++){
        #pragma unroll
        for (int half = 0; half < 2; half++){
            int mm = bm0 + wm + f*16 + gid + half*8;
            if (mm >= M) continue;
            float inv = 0.f;
            if (which == 0){
                float rs = g_rs2[mm];
                inv = (rs > 0.f) ? (1.f / rs) : 0.f;
            }
            #pragma unroll
            for (int j = 0; j < NF; j++){
                int col = wn + j*8 + tig*2;
                float v0 = d[f][j][half*2+0];
                float v1 = d[f][j][half*2+1];
                size_t o = (size_t)mm*128 + col;
                if (which == 0){
                    __stcs((float2*)&out[o],        make_float2(eluf(v0*inv), eluf(v1*inv)));
                    __stcs((float2*)&out[OFF2 + o], make_float2(eluf(v0),     eluf(v1)));
                } else {
                    __stcs((float2*)&out[OFF3 + o], make_float2(eluf(v0), eluf(v1)));
                }
            }
        }
    }
}

// ---------------- launcher ----------------
extern "C" void kernel_launch(void* const* d_in, const int* in_sizes, int n_in,
                              void* d_out, int out_size){
    const float* x    = (const float*)d_in[0];
    const float* rel  = (const float*)d_in[1];
    const float* eemb = (const float*)d_in[2];
    const float* ah   = (const float*)d_in[3];
    const float* a2h  = (const float*)d_in[4];
    const float* W    = (const float*)d_in[5];
    const float* ao   = (const float*)d_in[6];
    const float* a2o  = (const float*)d_in[7];
    const int* el  = (const int*)d_in[8];
    const int* et  = (const int*)d_in[9];
    const int* eln = (const int*)d_in[10];
    const int* etn = (const int*)d_in[11];
    float* out = (float*)d_out;

    const int GB = (NN + 127) / 128;   // 391

    // fused setup: hist + weight prep (independent work, one launch)
    k_setup1<<<HIST_BLKS + PREP_BLKS, 256>>>(el, eln, ah, a2h, ao, a2o, rel, W, out);
    // fused: scan + srel + sdots1
    k_setup2<<<7 + 6250, 256>>>(x, rel);
    k_scatter<<<HIST_BLKS, 256>>>(el, et, eln, etn);

    // layer 1  (k_edge1 stays in the ncu capture slot)
    k_edge1<<<6250, 256>>>(x, eemb, rel);
    k_tgemm1<<<dim3(GB, 2), 256>>>(x);

    // layer 2
    k_sdots2<<<6250, 256>>>();
    k_edge2<<<6250, 256>>>();
    k_tgemm2<<<dim3(GB, 2), 256>>>(out);
}